// round 1
// baseline (speedup 1.0000x reference)
#include <cuda_runtime.h>

#define TILE_M   128
#define KC       32
#define NTHREADS 256
#define NE       64
#define ND       1024
#define NSEQ     4096
#define NTOK     65536
#define NCHUNK   (ND / KC)

// -------- global -> register chunk load (coalesced float4) --------
#define LOAD_CHUNK(k0)                                                        \
    {                                                                         \
        _Pragma("unroll")                                                     \
        for (int i = 0; i < 4; i++) {                                         \
            int j = tid + NTHREADS * i;                                       \
            int m = j >> 3, c = j & 7;                                        \
            la[i] = *reinterpret_cast<const float4*>(                         \
                tokens + (size_t)(block_m + m) * ND + (k0) + 4 * c);          \
        }                                                                     \
        _Pragma("unroll")                                                     \
        for (int i = 0; i < 2; i++) {                                         \
            int j = tid + NTHREADS * i;                                       \
            int e = j >> 3, c = j & 7;                                        \
            lw[i] = *reinterpret_cast<const float4*>(                         \
                Wg + (size_t)e * ND + (k0) + 4 * c);                          \
        }                                                                     \
    }

// -------- register -> smem store (k-major transpose) --------
#define STORE_CHUNK(buf)                                                      \
    {                                                                         \
        _Pragma("unroll")                                                     \
        for (int i = 0; i < 4; i++) {                                         \
            int j = tid + NTHREADS * i;                                       \
            int m = j >> 3, c = j & 7;                                        \
            sA[buf][4 * c + 0][m] = la[i].x;                                  \
            sA[buf][4 * c + 1][m] = la[i].y;                                  \
            sA[buf][4 * c + 2][m] = la[i].z;                                  \
            sA[buf][4 * c + 3][m] = la[i].w;                                  \
        }                                                                     \
        _Pragma("unroll")                                                     \
        for (int i = 0; i < 2; i++) {                                         \
            int j = tid + NTHREADS * i;                                       \
            int e = j >> 3, c = j & 7;                                        \
            sW[buf][4 * c + 0][e] = lw[i].x;                                  \
            sW[buf][4 * c + 1][e] = lw[i].y;                                  \
            sW[buf][4 * c + 2][e] = lw[i].z;                                  \
            sW[buf][4 * c + 3][e] = lw[i].w;                                  \
        }                                                                     \
    }

__global__ __launch_bounds__(NTHREADS, 2)
void router_kernel(const float* __restrict__ tokens,
                   const int* __restrict__ t_arr,
                   const float* __restrict__ Wg,
                   const float* __restrict__ bg,
                   float* __restrict__ out)
{
    // exactly 48 KB static smem: sA 32 KB + sW 16 KB. Epilogue logits
    // (128 x 64 fp32 = 32 KB) overlay sA with XOR swizzle.
    __shared__ __align__(16) float sA[2][KC][TILE_M];
    __shared__ __align__(16) float sW[2][KC][NE];

    const int tid = threadIdx.x;
    const int block_m = blockIdx.x * TILE_M;

    const int tg = tid & 15;   // token group: tokens tg*8 .. tg*8+7
    const int eg = tid >> 4;   // expert group: experts eg*4 .. eg*4+3

    float acc[8][4];
#pragma unroll
    for (int i = 0; i < 8; i++)
#pragma unroll
        for (int j = 0; j < 4; j++) acc[i][j] = 0.0f;

    float4 la[4];
    float4 lw[2];

    LOAD_CHUNK(0);
    STORE_CHUNK(0);
    __syncthreads();

    for (int chunk = 0; chunk < NCHUNK; chunk++) {
        const int buf = chunk & 1;
        if (chunk + 1 < NCHUNK) {
            LOAD_CHUNK((chunk + 1) * KC);
        }
#pragma unroll 8
        for (int kk = 0; kk < KC; kk++) {
            float4 a0 = *reinterpret_cast<const float4*>(&sA[buf][kk][tg * 8]);
            float4 a1 = *reinterpret_cast<const float4*>(&sA[buf][kk][tg * 8 + 4]);
            float4 wv = *reinterpret_cast<const float4*>(&sW[buf][kk][eg * 4]);
            float av[8] = {a0.x, a0.y, a0.z, a0.w, a1.x, a1.y, a1.z, a1.w};
            float wl[4] = {wv.x, wv.y, wv.z, wv.w};
#pragma unroll
            for (int i = 0; i < 8; i++)
#pragma unroll
                for (int j = 0; j < 4; j++)
                    acc[i][j] = fmaf(av[i], wl[j], acc[i][j]);
        }
        if (chunk + 1 < NCHUNK) {
            STORE_CHUNK(buf ^ 1);   // disjoint from compute buffer: safe pre-sync
            __syncthreads();
        }
    }

    // ---------------- epilogue ----------------
    __syncthreads();   // done reading sA/sW; safe to overlay logits
    float* slog = &sA[0][0][0];   // [TILE_M][NE] with column swizzle e ^ (m & 31)

    // scatter logits (+bias) into smem
#pragma unroll
    for (int i = 0; i < 8; i++) {
        const int m = tg * 8 + i;
        const int msw = m & 31;
#pragma unroll
        for (int j = 0; j < 4; j++) {
            const int e = eg * 4 + j;
            slog[m * NE + (e ^ msw)] = acc[i][j] + __ldg(&bg[e]);
        }
    }
    __syncthreads();

    if (tid < TILE_M) {
        const int m = tid;
        const int gtok = block_m + m;
        const int b = gtok / NSEQ;
        const float cap = 0.5f + 1.1f * ((float)t_arr[b] / 1000.0f);
        const int msw = m & 31;
        float* row = slog + m * NE;

        // softmax (numerically identical structure to reference: max-sub, exp, /sum)
        float mx = -3.402823466e38f;
#pragma unroll 8
        for (int e = 0; e < NE; e++) mx = fmaxf(mx, row[e ^ msw]);

        float s = 0.0f;
#pragma unroll 4
        for (int e = 0; e < NE; e++) {
            const float v = expf(row[e ^ msw] - mx);
            s += v;
            row[e ^ msw] = v;
        }
        const float inv = 1.0f / s;

        // routing floor: alpha = 0.15 -> q = 0.85*p + 0.15/64
        // hard cap: excess / headroom accumulation
        float summin = 0.0f, sumex = 0.0f;
#pragma unroll 8
        for (int e = 0; e < NE; e++) {
            const float q = 0.85f * (row[e ^ msw] * inv) + (0.15f / 64.0f);
            row[e ^ msw] = q;
            const float c = fminf(q, cap);
            summin += c;
            sumex += q - c;
        }
        const float hs = fmaxf(64.0f * cap - summin, 1e-8f);
        const float scale = sumex / hs;

        // redistribution + top-2 (strict > ascending scan == jax tie-to-lowest-index)
        float v1 = -1.0f, v2 = -1.0f;
        int i1 = 0, i2 = 0;
#pragma unroll 8
        for (int e = 0; e < NE; e++) {
            const float q = row[e ^ msw];
            const float c = fminf(q, cap);
            const float f = c + scale * (cap - c);
            if (f > v1) {
                v2 = v1; i2 = i1;
                v1 = f;  i1 = e;
            } else if (f > v2) {
                v2 = f; i2 = e;
            }
        }

        // sparse gate row: zeros + two scalar overwrites (same-thread order preserved)
        float* orow = out + (size_t)gtok * NE;
        const float4 z = make_float4(0.f, 0.f, 0.f, 0.f);
#pragma unroll
        for (int u = 0; u < 16; u++) reinterpret_cast<float4*>(orow)[u] = z;
        orow[i1] = v1;
        orow[i2] = v2;
    }
}

extern "C" void kernel_launch(void* const* d_in, const int* in_sizes, int n_in,
                              void* d_out, int out_size)
{
    const float* tokens = (const float*)d_in[0];   // (16, 4096, 1024) f32
    const int*   t_arr  = (const int*)d_in[1];     // (16,) i32
    const float* Wg     = (const float*)d_in[2];   // (64, 1024) f32
    const float* bg     = (const float*)d_in[3];   // (64,) f32
    float*       out    = (float*)d_out;           // (16, 4096, 64) f32

    router_kernel<<<NTOK / TILE_M, NTHREADS>>>(tokens, t_arr, Wg, bg, out);
}